// round 7
// baseline (speedup 1.0000x reference)
#include <cuda_runtime.h>
#include <cuda_fp16.h>

#define S_LEN 2048
#define NHEAD 16
#define DHEAD 64
#define BM 64
#define BN 64
#define KSTRH 72    // K smem stride in halves: conflict-free LDS.32 B-frags
#define VTSTRH 72   // Vt smem stride in halves (Vt[d][key])

static __device__ __forceinline__ unsigned packh2(float lo, float hi) {
    __half2 h = __floats2half2_rn(lo, hi);
    return *(unsigned*)&h;
}

static __device__ __forceinline__ void mma_f16(float* d,
                                               unsigned a0, unsigned a1, unsigned a2, unsigned a3,
                                               unsigned b0, unsigned b1) {
    asm volatile("mma.sync.aligned.m16n8k16.row.col.f32.f16.f16.f32 "
                 "{%0,%1,%2,%3}, {%4,%5,%6,%7}, {%8,%9}, {%0,%1,%2,%3};"
                 : "+f"(d[0]), "+f"(d[1]), "+f"(d[2]), "+f"(d[3])
                 : "r"(a0), "r"(a1), "r"(a2), "r"(a3), "r"(b0), "r"(b1));
}

__global__ __launch_bounds__(128, 3)
void attn_tc4_kernel(const float* __restrict__ Q, const float* __restrict__ K,
                     const float* __restrict__ V, float* __restrict__ Out) {
    extern __shared__ __half smh[];
    __half* Ksh = smh;                    // [BN][KSTRH]  K natural [key][d], half
    __half* Vth = smh + BN * KSTRH;       // [DHEAD][VTSTRH]  V transposed [d][key], half

    const int qt   = (gridDim.x - 1) - blockIdx.x;   // heavy tiles first
    const int bh   = blockIdx.y;
    const int b    = bh >> 4;
    const int h    = bh & 15;
    const int qrow = qt * BM;

    const float* Kg = K + (size_t)bh * S_LEN * DHEAD;
    const float* Vg = V + (size_t)bh * S_LEN * DHEAD;

    const int tid  = threadIdx.x;
    const int warp = tid >> 5;
    const int lane = tid & 31;
    const int g    = lane >> 2;
    const int t4   = lane & 3;
    const int r0w  = warp << 4;
    const int row0 = qrow + r0w + g;
    const int row1 = row0 + 8;

    // ---- Q A-fragments (fp16, pre-scaled by 1/8) straight from global ----
    // a0={Q[g][16ks+2t4,+1]}, a1=row g+8, a2={..+8,+9}, a3=row g+8 hi
    unsigned qa[4][4];
    {
        const float* Qg = Q + ((size_t)bh * S_LEN + qrow + r0w) * DHEAD;
        #pragma unroll
        for (int ks = 0; ks < 4; ks++) {
            const float* rp = Qg + g * DHEAD + 16 * ks + 2 * t4;
            float2 xl = *(const float2*)rp;                   // row g,  k lo
            float2 xh = *(const float2*)(rp + 8);             // row g,  k hi
            float2 yl = *(const float2*)(rp + 8 * DHEAD);     // row g+8, k lo
            float2 yh = *(const float2*)(rp + 8 * DHEAD + 8); // row g+8, k hi
            qa[ks][0] = packh2(0.125f * xl.x, 0.125f * xl.y);
            qa[ks][1] = packh2(0.125f * yl.x, 0.125f * yl.y);
            qa[ks][2] = packh2(0.125f * xh.x, 0.125f * xh.y);
            qa[ks][3] = packh2(0.125f * yh.x, 0.125f * yh.y);
        }
    }

    float o[8][4];
    #pragma unroll
    for (int nt = 0; nt < 8; nt++)
        #pragma unroll
        for (int e = 0; e < 4; e++) o[nt][e] = 0.f;

    float m0 = -1e30f, m1 = -1e30f, l0 = 0.f, l1 = 0.f;

    // staging index precompute
    const int kr_row = tid >> 4;              // K: key row
    const int kr_d4  = (tid & 15) << 2;       // K: d offset
    const int v_rp   = tid & 15;              // V: key-pair base (keys 2rp, 2rp+1)
    const int v_h    = tid >> 4;              // V: d-block

    for (int kt = 0; kt <= qt; kt++) {
        const float* Kgt = Kg + (size_t)kt * BN * DHEAD;
        const float* Vgt = Vg + (size_t)kt * BN * DHEAD;

        // ---- Prefetch K/V tile into regs before the sync ----
        float4 kr[8];
        #pragma unroll
        for (int it = 0; it < 8; it++) {
            int i = tid + (it << 7);
            kr[it] = *(const float4*)(Kgt + (i >> 4) * DHEAD + ((i & 15) << 2));
        }
        float4 va[2][2][2];   // [u: d-half][kh: key-half][pair row]
        #pragma unroll
        for (int u = 0; u < 2; u++)
            #pragma unroll
            for (int kh = 0; kh < 2; kh++) {
                int key = 2 * (v_rp + 16 * kh);
                int dv  = 4 * v_h + 32 * u;
                const float* vp = Vgt + key * DHEAD + dv;
                va[u][kh][0] = *(const float4*)vp;
                va[u][kh][1] = *(const float4*)(vp + DHEAD);
            }

        __syncthreads();   // previous iteration's Ksh/Vth readers done

        // ---- Store K (natural, half) ----
        #pragma unroll
        for (int it = 0; it < 8; it++) {
            int i  = tid + (it << 7);
            int r  = i >> 4;
            int d4 = (i & 15) << 2;
            __half2* dst = (__half2*)(Ksh + r * KSTRH + d4);
            dst[0] = __floats2half2_rn(kr[it].x, kr[it].y);
            dst[1] = __floats2half2_rn(kr[it].z, kr[it].w);
        }
        // ---- Store V transposed: Vt[d][key] (half2 spans key pair) ----
        #pragma unroll
        for (int u = 0; u < 2; u++)
            #pragma unroll
            for (int kh = 0; kh < 2; kh++) {
                int key = 2 * (v_rp + 16 * kh);
                int dv  = 4 * v_h + 32 * u;
                float4 v0 = va[u][kh][0], v1 = va[u][kh][1];
                *(__half2*)(Vth + (dv + 0) * VTSTRH + key) = __floats2half2_rn(v0.x, v1.x);
                *(__half2*)(Vth + (dv + 1) * VTSTRH + key) = __floats2half2_rn(v0.y, v1.y);
                *(__half2*)(Vth + (dv + 2) * VTSTRH + key) = __floats2half2_rn(v0.z, v1.z);
                *(__half2*)(Vth + (dv + 3) * VTSTRH + key) = __floats2half2_rn(v0.w, v1.w);
            }
        __syncthreads();

        // ---- GEMM1: S = (Q*scale) K^T ----
        float s[8][4];
        #pragma unroll
        for (int nt = 0; nt < 8; nt++) {
            s[nt][0] = 0.f; s[nt][1] = 0.f; s[nt][2] = 0.f; s[nt][3] = 0.f;
            const __half* kb = Ksh + (g + 8 * nt) * KSTRH + 2 * t4;
            #pragma unroll
            for (int ks = 0; ks < 4; ks++) {
                unsigned b0 = *(const unsigned*)(kb + 16 * ks);       // K[key][16ks+2t4,+1]
                unsigned b1 = *(const unsigned*)(kb + 16 * ks + 8);   // K[key][16ks+2t4+8,+9]
                mma_f16(s[nt], qa[ks][0], qa[ks][1], qa[ks][2], qa[ks][3], b0, b1);
            }
        }

        // ---- Causal mask (diagonal tile only) ----
        if (kt == qt) {
            const int colb = (kt << 6) + 2 * t4;
            #pragma unroll
            for (int nt = 0; nt < 8; nt++) {
                int c0 = colb + 8 * nt, c1 = c0 + 1;
                if (c0 > row0) s[nt][0] = -10000.0f;
                if (c1 > row0) s[nt][1] = -10000.0f;
                if (c0 > row1) s[nt][2] = -10000.0f;
                if (c1 > row1) s[nt][3] = -10000.0f;
            }
        }

        // ---- Online softmax; P packed to half2 in regs ----
        float mx0 = -1e30f, mx1 = -1e30f;
        #pragma unroll
        for (int nt = 0; nt < 8; nt++) {
            mx0 = fmaxf(mx0, fmaxf(s[nt][0], s[nt][1]));
            mx1 = fmaxf(mx1, fmaxf(s[nt][2], s[nt][3]));
        }
        mx0 = fmaxf(mx0, __shfl_xor_sync(0xffffffffu, mx0, 1));
        mx0 = fmaxf(mx0, __shfl_xor_sync(0xffffffffu, mx0, 2));
        mx1 = fmaxf(mx1, __shfl_xor_sync(0xffffffffu, mx1, 1));
        mx1 = fmaxf(mx1, __shfl_xor_sync(0xffffffffu, mx1, 2));

        float mn0 = fmaxf(m0, mx0), mn1 = fmaxf(m1, mx1);
        float cr0 = __expf(m0 - mn0), cr1 = __expf(m1 - mn1);

        unsigned ph[8][2];   // ph[nt][0]=pack(row g cols), [1]=pack(row g+8 cols)
        float sum0 = 0.f, sum1 = 0.f;
        #pragma unroll
        for (int nt = 0; nt < 8; nt++) {
            float p0 = __expf(s[nt][0] - mn0);
            float p1 = __expf(s[nt][1] - mn0);
            float p2 = __expf(s[nt][2] - mn1);
            float p3 = __expf(s[nt][3] - mn1);
            sum0 += p0 + p1; sum1 += p2 + p3;
            ph[nt][0] = packh2(p0, p1);
            ph[nt][1] = packh2(p2, p3);
        }
        sum0 += __shfl_xor_sync(0xffffffffu, sum0, 1);
        sum0 += __shfl_xor_sync(0xffffffffu, sum0, 2);
        sum1 += __shfl_xor_sync(0xffffffffu, sum1, 1);
        sum1 += __shfl_xor_sync(0xffffffffu, sum1, 2);

        l0 = l0 * cr0 + sum0;
        l1 = l1 * cr1 + sum1;
        m0 = mn0; m1 = mn1;

        #pragma unroll
        for (int nt = 0; nt < 8; nt++) {
            o[nt][0] *= cr0; o[nt][1] *= cr0;
            o[nt][2] *= cr1; o[nt][3] *= cr1;
        }

        // ---- GEMM2: O += P V.  A = repacked C-frags (identity k-map). ----
        #pragma unroll
        for (int ks = 0; ks < 4; ks++) {
            unsigned a0 = ph[2 * ks][0];
            unsigned a1 = ph[2 * ks][1];
            unsigned a2 = ph[2 * ks + 1][0];
            unsigned a3 = ph[2 * ks + 1][1];
            const __half* vb = Vth + 16 * ks + 2 * t4;
            #pragma unroll
            for (int nt = 0; nt < 8; nt++) {
                const __half* vp = vb + (g + 8 * nt) * VTSTRH;
                unsigned b0 = *(const unsigned*)vp;        // V[16ks+2t4,+1][d]
                unsigned b1 = *(const unsigned*)(vp + 8);  // V[16ks+2t4+8,+9][d]
                mma_f16(o[nt], a0, a1, a2, a3, b0, b1);
            }
        }
    }

    // ---- Epilogue: normalize, write Out[b][s][h*64 + d] ----
    const float inv0 = 1.f / l0;
    const float inv1 = 1.f / l1;
    float* Op0 = Out + ((size_t)b * S_LEN + row0) * (NHEAD * DHEAD) + h * DHEAD;
    float* Op1 = Out + ((size_t)b * S_LEN + row1) * (NHEAD * DHEAD) + h * DHEAD;
    #pragma unroll
    for (int nt = 0; nt < 8; nt++) {
        int col = 8 * nt + 2 * t4;
        *(float2*)(Op0 + col) = make_float2(o[nt][0] * inv0, o[nt][1] * inv0);
        *(float2*)(Op1 + col) = make_float2(o[nt][2] * inv1, o[nt][3] * inv1);
    }
}

extern "C" void kernel_launch(void* const* d_in, const int* in_sizes, int n_in,
                              void* d_out, int out_size) {
    (void)in_sizes; (void)n_in; (void)out_size;
    const float* q = (const float*)d_in[0];
    const float* k = (const float*)d_in[1];
    const float* v = (const float*)d_in[2];
    float* out = (float*)d_out;

    const int smem_bytes = (BN * KSTRH + DHEAD * VTSTRH) * (int)sizeof(__half);  // 18432 B
    cudaFuncSetAttribute(attn_tc4_kernel,
                         cudaFuncAttributeMaxDynamicSharedMemorySize, smem_bytes);

    dim3 grid(S_LEN / BM, 4 * NHEAD);   // (32, 64)
    attn_tc4_kernel<<<grid, 128, smem_bytes>>>(q, k, v, out);
}